// round 14
// baseline (speedup 1.0000x reference)
#include <cuda_runtime.h>
#include <math.h>

#define NB    32
#define LEN   4096
#define CH    128
#define NF    2048      // packed complex FFT size (LEN/2)
#define TOPK  64
#define NTHR  128
#define VPT   17        // 128*17 = 2176 >= 2049 bins
#define PADB  2180      // PADi(2048)=2176 is the Nyquist slot

// ---------------- device globals (scratch; no runtime allocation) ----------------
__device__ float  g_work[(size_t)NB * CH * LEN];   // 64 MB, (B,C,L)
__device__ float2 g_tw2[15 * 16];                  // stage2: W_2048^(8*m*r), [r-1][m]
__device__ float2 g_tw3[7 * 256];                  // stage3: W_2048^(j*r),   [r-1][j]
__device__ float2 g_tsplit[NF];                    // e^{-pi i k / 2048}

// ---------------- twiddle init ----------------
__global__ void init_twiddles_k() {
    int i = blockIdx.x * blockDim.x + threadIdx.x;
    const double PI = 3.14159265358979323846;
    if (i < NF) {
        double b = -PI * (double)i / (double)NF;
        g_tsplit[i] = make_float2((float)cos(b), (float)sin(b));
    }
    if (i < 15 * 16) {
        int r = i / 16 + 1, m = i % 16;
        double a = -2.0 * PI * (double)(8 * m * r) / (double)NF;
        g_tw2[i] = make_float2((float)cos(a), (float)sin(a));
    }
    if (i < 7 * 256) {
        int r = i / 256 + 1, j = i % 256;
        double a = -2.0 * PI * (double)(j * r) / (double)NF;
        g_tw3[i] = make_float2((float)cos(a), (float)sin(a));
    }
}

// ------------- transposes: 256(L) x 32(C) per block, 8 tiles, blockDim (8,32) -------------
__global__ void transpose_in_k(const float* __restrict__ in) {
    __shared__ float tile[8][32][33];
    int b = blockIdx.z;
    int l0 = blockIdx.x << 8, c0 = blockIdx.y << 5;
    int x = threadIdx.x, y = threadIdx.y;
    const float* p = in + (size_t)b * LEN * CH + c0 + 4 * x;
    float4 v[8];
#pragma unroll
    for (int h = 0; h < 8; h++)
        v[h] = __ldcs(reinterpret_cast<const float4*>(p + (size_t)(l0 + 32 * h + y) * CH));
#pragma unroll
    for (int h = 0; h < 8; h++) {
        tile[h][y][4 * x + 0] = v[h].x; tile[h][y][4 * x + 1] = v[h].y;
        tile[h][y][4 * x + 2] = v[h].z; tile[h][y][4 * x + 3] = v[h].w;
    }
    __syncthreads();
    float* q = g_work + (size_t)b * CH * LEN + (size_t)(c0 + y) * LEN + l0;
#pragma unroll
    for (int h = 0; h < 8; h++) {
        float4 w;
        w.x = tile[h][4 * x + 0][y]; w.y = tile[h][4 * x + 1][y];
        w.z = tile[h][4 * x + 2][y]; w.w = tile[h][4 * x + 3][y];
        *reinterpret_cast<float4*>(q + 32 * h + 4 * x) = w;
    }
}

__global__ void transpose_out_k(float* __restrict__ out) {
    __shared__ float tile[8][32][33];
    int b = blockIdx.z;
    int l0 = blockIdx.x << 8, c0 = blockIdx.y << 5;
    int x = threadIdx.x, y = threadIdx.y;
    const float* p = g_work + (size_t)b * CH * LEN + (size_t)(c0 + y) * LEN + l0;
    float4 v[8];
#pragma unroll
    for (int h = 0; h < 8; h++)
        v[h] = __ldcs(reinterpret_cast<const float4*>(p + 32 * h + 4 * x));
#pragma unroll
    for (int h = 0; h < 8; h++) {
        tile[h][4 * x + 0][y] = v[h].x; tile[h][4 * x + 1][y] = v[h].y;
        tile[h][4 * x + 2][y] = v[h].z; tile[h][4 * x + 3][y] = v[h].w;
    }
    __syncthreads();
    float* q = out + (size_t)b * LEN * CH + c0 + 4 * x;
#pragma unroll
    for (int h = 0; h < 8; h++) {
        float4 w;
        w.x = tile[h][y][4 * x + 0]; w.y = tile[h][y][4 * x + 1];
        w.z = tile[h][y][4 * x + 2]; w.w = tile[h][y][4 * x + 3];
        __stcs(reinterpret_cast<float4*>(q + (size_t)(l0 + 32 * h + y) * CH), w);
    }
}

// ---------------- complex helpers (scalar) ----------------
__device__ __forceinline__ int PADi(int i) { return i + (i >> 4); }
__device__ __forceinline__ float2 cadd(float2 a, float2 b) { return make_float2(a.x + b.x, a.y + b.y); }
__device__ __forceinline__ float2 csub(float2 a, float2 b) { return make_float2(a.x - b.x, a.y - b.y); }
__device__ __forceinline__ float2 cmulf(float2 a, float2 b) {
    return make_float2(a.x * b.x - a.y * b.y, a.x * b.y + a.y * b.x);
}
__device__ __forceinline__ float2 mnegi(float2 a) { return make_float2(a.y, -a.x); } // a * (-i)
// a * (c - i s)
__device__ __forceinline__ float2 mulW(float2 a, float c, float s) {
    return make_float2(a.x * c + a.y * s, a.y * c - a.x * s);
}

__device__ __forceinline__ void radix8(const float2* c, float2* d) {
    float2 s0 = cadd(c[0], c[4]), s1 = csub(c[0], c[4]);
    float2 s2 = cadd(c[2], c[6]), s3 = mnegi(csub(c[2], c[6]));
    float2 E0 = cadd(s0, s2), E2 = csub(s0, s2);
    float2 E1 = cadd(s1, s3), E3 = csub(s1, s3);
    float2 u0 = cadd(c[1], c[5]), u1 = csub(c[1], c[5]);
    float2 u2 = cadd(c[3], c[7]), u3 = mnegi(csub(c[3], c[7]));
    float2 O0 = cadd(u0, u2), O2 = csub(u0, u2);
    float2 O1 = cadd(u1, u3), O3 = csub(u1, u3);
    const float r2 = 0.70710678118654752f;
    float2 T1 = make_float2(r2 * (O1.x + O1.y), r2 * (O1.y - O1.x));   // W8^1*O1
    float2 T2 = mnegi(O2);                                             // W8^2*O2
    float2 T3 = make_float2(r2 * (O3.y - O3.x), r2 * (-O3.x - O3.y));  // W8^3*O3
    d[0] = cadd(E0, O0); d[4] = csub(E0, O0);
    d[1] = cadd(E1, T1); d[5] = csub(E1, T1);
    d[2] = cadd(E2, T2); d[6] = csub(E2, T2);
    d[3] = cadd(E3, T3); d[7] = csub(E3, T3);
}

// in-place DFT-16 on v[0..15]
__device__ __forceinline__ void dft16_ip(float2* v) {
    float2 e[8], o[8];
#pragma unroll
    for (int r = 0; r < 8; r++) { e[r] = v[2 * r]; o[r] = v[2 * r + 1]; }
    float2 E[8], O[8];
    radix8(e, E);
    radix8(o, O);
    const float C1 = 0.92387953251128674f, S1 = 0.38268343236508978f;
    const float R2 = 0.70710678118654752f;
    float2 T[8];
    T[0] = O[0];
    T[1] = mulW(O[1], C1, S1);
    T[2] = mulW(O[2], R2, R2);
    T[3] = mulW(O[3], S1, C1);
    T[4] = mnegi(O[4]);
    T[5] = mnegi(mulW(O[5], C1, S1));
    T[6] = mnegi(mulW(O[6], R2, R2));
    T[7] = mnegi(mulW(O[7], S1, C1));
#pragma unroll
    for (int k = 0; k < 8; k++) {
        v[k]     = cadd(E[k], T[k]);
        v[k + 8] = csub(E[k], T[k]);
    }
}

// stage 1 variant A: input directly from GLOBAL (coalesced LDG.64, MLP=16)
__device__ __forceinline__ void stage1_from_global(const float2* __restrict__ gin,
                                                   float2* buf, int t) {
    float2 v[16];
#pragma unroll
    for (int r = 0; r < 16; r++) v[r] = __ldcs(&gin[t + (r << 7)]);
    dft16_ip(v);
    int dbase = t << 4;
#pragma unroll
    for (int r = 0; r < 16; r++) buf[PADi(dbase + r)] = v[r];
    __syncthreads();
}

// stage 1 variant B: in-place from smem
__device__ __forceinline__ void stage1_ip(float2* buf, int t) {
    float2 v[16];
#pragma unroll
    for (int r = 0; r < 16; r++) v[r] = buf[PADi(t + (r << 7))];
    dft16_ip(v);
    __syncthreads();
    int dbase = t << 4;
#pragma unroll
    for (int r = 0; r < 16; r++) buf[PADi(dbase + r)] = v[r];
    __syncthreads();
}

// stage 2: R=16, Ns=16, in place; twiddles from coalesced table g_tw2[r-1][m]
__device__ __forceinline__ void stage2_ip(float2* buf, int t) {
    float2 v[16];
#pragma unroll
    for (int r = 0; r < 16; r++) v[r] = buf[PADi(t + (r << 7))];
    int m = t & 15;
#pragma unroll
    for (int r = 1; r < 16; r++) v[r] = cmulf(v[r], g_tw2[((r - 1) << 4) + m]);
    dft16_ip(v);
    __syncthreads();
    int dbase = ((t >> 4) << 8) + (t & 15);
#pragma unroll
    for (int r = 0; r < 16; r++) buf[PADi(dbase + (r << 4))] = v[r];
    __syncthreads();
}

// stage 3: R=8, Ns=256, in place; twiddles from coalesced table g_tw3[r-1][j]
__device__ __forceinline__ void stage3_ip(float2* buf, int t) {
#pragma unroll
    for (int h = 0; h < 2; h++) {
        int j = t + (h << 7);   // 0..255
        float2 v[8], d[8];
#pragma unroll
        for (int r = 0; r < 8; r++) v[r] = buf[PADi(j + (r << 8))];
#pragma unroll
        for (int r = 1; r < 8; r++) v[r] = cmulf(v[r], g_tw3[((r - 1) << 8) + j]);
        radix8(v, d);
#pragma unroll
        for (int r = 0; r < 8; r++) buf[PADi(j + (r << 8))] = d[r];
    }
    __syncthreads();
}

// stage 3 variant: results go straight to GLOBAL with conj + 1/N scale
__device__ __forceinline__ void stage3_to_global(const float2* buf,
                                                 float2* __restrict__ gout, int t) {
    const float invn = 1.0f / (float)NF;
#pragma unroll
    for (int h = 0; h < 2; h++) {
        int j = t + (h << 7);   // 0..255
        float2 v[8], d[8];
#pragma unroll
        for (int r = 0; r < 8; r++) v[r] = buf[PADi(j + (r << 8))];
#pragma unroll
        for (int r = 1; r < 8; r++) v[r] = cmulf(v[r], g_tw3[((r - 1) << 8) + j]);
        radix8(v, d);
        // F = NF * conj(z') ; z'[n] = conj(F[n])/NF
#pragma unroll
        for (int r = 0; r < 8; r++)
            gout[j + (r << 8)] = make_float2(d[r].x * invn, -d[r].y * invn);
    }
}

// ---------------- main per-row kernel ----------------
__global__ void __launch_bounds__(NTHR, 8) fourier_rows_k() {
    __shared__ float2 buf[PADB];
    __shared__ unsigned hist[2][256];
    __shared__ unsigned selmask[65];
    __shared__ unsigned warpsum[4];
    __shared__ unsigned scal[2];

    int t = threadIdx.x;
    float2* rp2 = reinterpret_cast<float2*>(g_work + (size_t)blockIdx.x * LEN);

    // ---- forward FFT: stage1 straight from global (z[n] = x[2n] + i x[2n+1]) ----
    stage1_from_global(rp2, buf, t);
    stage2_ip(buf, t);
    stage3_ip(buf, t);          // Z in buf

    // rfft split, in place, pairwise (k, 2048-k); one thread owns both slots.
    // X[k] = E + W*O ; X[2048-k] = conj(E - W*O)
    for (int k = t; k <= NF / 2; k += NTHR) {
        float2 Zk = buf[PADi(k & (NF - 1))];
        float2 Zn = buf[PADi((NF - k) & (NF - 1))];
        float2 W  = g_tsplit[k];
        float2 E  = make_float2(0.5f * (Zk.x + Zn.x), 0.5f * (Zk.y - Zn.y));
        float2 D  = make_float2(Zk.x - Zn.x, Zk.y + Zn.y);
        float2 O  = make_float2(0.5f * D.y, -0.5f * D.x);   // D/(2i)
        float2 P  = cmulf(O, W);
        buf[PADi(k)]      = make_float2(E.x + P.x, E.y + P.y);
        buf[PADi(NF - k)] = make_float2(E.x - P.x, -(E.y - P.y));  // conj(E-P)
    }
    // zero select scratch while we're here (before the barrier)
    if (t < 65) selmask[t] = 0u;
    hist[0][t] = 0u; hist[0][t + 128] = 0u;
    __syncthreads();

    // keys = bits(|X|^2), thread t owns bins t*VPT .. t*VPT+VPT-1
    unsigned keys[VPT];
#pragma unroll
    for (int v = 0; v < VPT; v++) {
        int k = t * VPT + v;
        if (k <= NF) {
            float2 X = buf[PADi(k)];
            keys[v] = __float_as_uint(X.x * X.x + X.y * X.y);
        } else {
            keys[v] = 0u;
        }
    }

    // radix-select the TOPK-th largest key: 4 passes of 8 bits, MSB first.
    // hist double-buffered: while warp0 scans hist[p], other threads zero hist[p^1].
    unsigned pref = 0u;
    int remain = TOPK;
#pragma unroll
    for (int pass = 0; pass < 4; pass++) {
        int shift = 24 - 8 * pass;
        int p = pass & 1;
        unsigned himask = (shift == 24) ? 0u : (0xFFFFFFFFu << (shift + 8));
#pragma unroll
        for (int v = 0; v < VPT; v++) {
            unsigned key = keys[v];
            unsigned bucket = ((key & himask) == (pref & himask))
                                  ? ((key >> shift) & 255u) : 0xFFFFu;
            // skip whole warp-round if no lane has a candidate (common after pass 1)
            unsigned anyb = __ballot_sync(0xFFFFFFFFu, bucket != 0xFFFFu);
            if (anyb) {
                unsigned mm = __match_any_sync(0xFFFFFFFFu, bucket);
                if (bucket != 0xFFFFu && (t & 31) == (__ffs(mm) - 1))
                    atomicAdd(&hist[p][bucket], (unsigned)__popc(mm));
            }
        }
        __syncthreads();
        if (t < 32) {
            unsigned cnts[8]; unsigned lsum = 0;
#pragma unroll
            for (int e = 0; e < 8; e++) { cnts[e] = hist[p][255 - (t * 8 + e)]; lsum += cnts[e]; }
            unsigned inc = lsum;
#pragma unroll
            for (int o = 1; o < 32; o <<= 1) {
                unsigned nn = __shfl_up_sync(0xFFFFFFFFu, inc, o);
                if (t >= o) inc += nn;
            }
            int excl = (int)(inc - lsum);  // keys strictly above this lane's range
            if (excl < remain && remain <= (int)inc) {
                int run = excl;
#pragma unroll
                for (int e = 0; e < 8; e++) {
                    if (run < remain && remain <= run + (int)cnts[e]) {
                        scal[0] = (unsigned)(255 - (t * 8 + e));
                        scal[1] = (unsigned)run;
                    }
                    run += (int)cnts[e];
                }
            }
        } else {
            // zero the other hist buffer for the next pass
            int q = p ^ 1;
            int i = t - 32;                       // 0..95
            hist[q][i] = 0u; hist[q][i + 96] = 0u;
            if (i < 64) hist[q][i + 192] = 0u;
        }
        __syncthreads();
        pref |= (scal[0] << shift);
        remain -= (int)scal[1];
    }
    unsigned Tkey = pref;   // exact key of the TOPK-th largest
    int extra = remain;     // ties (== Tkey) to keep, lowest bin index first

    // per-thread exclusive rank among ties (global order = bin index order)
    int local = 0;
#pragma unroll
    for (int v = 0; v < VPT; v++) {
        int k = t * VPT + v;
        if (k <= NF && keys[v] == Tkey) local++;
    }
    int inc2 = local;
#pragma unroll
    for (int o = 1; o < 32; o <<= 1) {
        int nn = __shfl_up_sync(0xFFFFFFFFu, inc2, o);
        if ((t & 31) >= o) inc2 += nn;
    }
    if ((t & 31) == 31) warpsum[t >> 5] = (unsigned)inc2;
    __syncthreads();
    if (t == 0) {
        unsigned acc = 0;
        for (int w = 0; w < 4; w++) { unsigned s = warpsum[w]; warpsum[w] = acc; acc += s; }
    }
    __syncthreads();
    int rank = (int)warpsum[t >> 5] + (inc2 - local);

    // build selection bitmask (only ~TOPK bits set -> few atomics)
#pragma unroll
    for (int v = 0; v < VPT; v++) {
        int k = t * VPT + v;
        if (k <= NF) {
            bool sel;
            if (keys[v] > Tkey) sel = true;
            else if (keys[v] == Tkey) { sel = (rank < extra); rank++; }
            else sel = false;
            if (sel) atomicOr(&selmask[k >> 5], 1u << (k & 31));
        }
    }
    __syncthreads();

    // rebuild conj(Z') from masked X, in place, pairwise; mask applied as predicate.
    for (int k = t; k <= NF / 2; k += NTHR) {
        bool sk = (selmask[k >> 5] >> (k & 31)) & 1u;
        int kn = NF - k;
        bool sn = (selmask[kn >> 5] >> (kn & 31)) & 1u;
        float2 Xk = buf[PADi(k)];
        float2 Xn = buf[PADi(kn)];   // k=0 -> Nyquist slot
        if (!sk) Xk = make_float2(0.f, 0.f);
        if (!sn) Xn = make_float2(0.f, 0.f);
        float2 W  = g_tsplit[k];
        float2 E  = make_float2(0.5f * (Xk.x + Xn.x), 0.5f * (Xk.y - Xn.y));
        float2 Dh = make_float2(0.5f * (Xk.x - Xn.x), 0.5f * (Xk.y + Xn.y)); // W^k O
        float2 O  = make_float2(Dh.x * W.x + Dh.y * W.y, Dh.y * W.x - Dh.x * W.y); // Dh*conj(W)
        float2 zck = make_float2(E.x - O.y, -(E.y + O.x));   // conj(Z'[k])
        float2 E2  = make_float2(0.5f * (Xn.x + Xk.x), 0.5f * (Xn.y - Xk.y));
        float2 Dh2 = make_float2(0.5f * (Xn.x - Xk.x), 0.5f * (Xn.y + Xk.y));
        float2 O2  = make_float2(-Dh2.x * W.x + Dh2.y * W.y, -Dh2.y * W.x - Dh2.x * W.y);
        float2 zcn = make_float2(E2.x - O2.y, -(E2.y + O2.x));
        buf[PADi(k)] = zck;
        if (k > 0) buf[PADi(NF - k)] = zcn;   // slot 2048 not part of Z'
    }
    __syncthreads();

    // ---- inverse FFT: F = FFT(conj(Z')) = NF * conj(z'); stage3 writes global ----
    stage1_ip(buf, t);
    stage2_ip(buf, t);
    stage3_to_global(buf, rp2, t);
}

// ---------------- launch ----------------
extern "C" void kernel_launch(void* const* d_in, const int* in_sizes, int n_in,
                              void* d_out, int out_size) {
    const float* x = (const float*)d_in[0];
    float* out = (float*)d_out;

    init_twiddles_k<<<(NF + 255) / 256, 256>>>();

    dim3 tb(8, 32);
    dim3 tg(LEN / 256, CH / 32, NB);
    transpose_in_k<<<tg, tb>>>(x);

    fourier_rows_k<<<NB * CH, NTHR>>>();

    transpose_out_k<<<tg, tb>>>(out);
}

// round 15
// speedup vs baseline: 1.1612x; 1.1612x over previous
#include <cuda_runtime.h>
#include <math.h>

#define NB    32
#define LEN   4096
#define CH    128
#define NF    2048      // packed complex FFT size (LEN/2)
#define TOPK  64
#define NTHR  128
#define VPT   17        // 128*17 = 2176 >= 2049 bins
#define PADB  2180      // PADi(2048)=2176 is the Nyquist slot

// ---------------- device globals (scratch; no runtime allocation) ----------------
__device__ float  g_work[(size_t)NB * CH * LEN];   // 64 MB, (B,C,L)
__device__ float2 g_tw2[15 * 16];                  // stage2: W_2048^(8*m*r), [r-1][m]
__device__ float2 g_tw3[7 * 256];                  // stage3: W_2048^(j*r),   [r-1][j]
__device__ float2 g_tsplit[NF];                    // e^{-pi i k / 2048}

// ---------------- twiddle init ----------------
__global__ void init_twiddles_k() {
    int i = blockIdx.x * blockDim.x + threadIdx.x;
    const double PI = 3.14159265358979323846;
    if (i < NF) {
        double b = -PI * (double)i / (double)NF;
        g_tsplit[i] = make_float2((float)cos(b), (float)sin(b));
    }
    if (i < 15 * 16) {
        int r = i / 16 + 1, m = i % 16;
        double a = -2.0 * PI * (double)(8 * m * r) / (double)NF;
        g_tw2[i] = make_float2((float)cos(a), (float)sin(a));
    }
    if (i < 7 * 256) {
        int r = i / 256 + 1, j = i % 256;
        double a = -2.0 * PI * (double)(j * r) / (double)NF;
        g_tw3[i] = make_float2((float)cos(a), (float)sin(a));
    }
}

// ------------- transposes: 128(L) x 32(C) per block, 4 tiles, blockDim (8,32) -------------
__global__ void transpose_in_k(const float* __restrict__ in) {
    __shared__ float tile[4][32][33];
    int b = blockIdx.z;
    int l0 = blockIdx.x << 7, c0 = blockIdx.y << 5;
    int x = threadIdx.x, y = threadIdx.y;
    const float* p = in + (size_t)b * LEN * CH + c0 + 4 * x;
    float4 v[4];
#pragma unroll
    for (int h = 0; h < 4; h++)
        v[h] = __ldcs(reinterpret_cast<const float4*>(p + (size_t)(l0 + 32 * h + y) * CH));
#pragma unroll
    for (int h = 0; h < 4; h++) {
        tile[h][y][4 * x + 0] = v[h].x; tile[h][y][4 * x + 1] = v[h].y;
        tile[h][y][4 * x + 2] = v[h].z; tile[h][y][4 * x + 3] = v[h].w;
    }
    __syncthreads();
    float* q = g_work + (size_t)b * CH * LEN + (size_t)(c0 + y) * LEN + l0;
#pragma unroll
    for (int h = 0; h < 4; h++) {
        float4 w;
        w.x = tile[h][4 * x + 0][y]; w.y = tile[h][4 * x + 1][y];
        w.z = tile[h][4 * x + 2][y]; w.w = tile[h][4 * x + 3][y];
        *reinterpret_cast<float4*>(q + 32 * h + 4 * x) = w;
    }
}

__global__ void transpose_out_k(float* __restrict__ out) {
    __shared__ float tile[4][32][33];
    int b = blockIdx.z;
    int l0 = blockIdx.x << 7, c0 = blockIdx.y << 5;
    int x = threadIdx.x, y = threadIdx.y;
    const float* p = g_work + (size_t)b * CH * LEN + (size_t)(c0 + y) * LEN + l0;
    float4 v[4];
#pragma unroll
    for (int h = 0; h < 4; h++)
        v[h] = __ldcs(reinterpret_cast<const float4*>(p + 32 * h + 4 * x));
#pragma unroll
    for (int h = 0; h < 4; h++) {
        tile[h][4 * x + 0][y] = v[h].x; tile[h][4 * x + 1][y] = v[h].y;
        tile[h][4 * x + 2][y] = v[h].z; tile[h][4 * x + 3][y] = v[h].w;
    }
    __syncthreads();
    float* q = out + (size_t)b * LEN * CH + c0 + 4 * x;
#pragma unroll
    for (int h = 0; h < 4; h++) {
        float4 w;
        w.x = tile[h][y][4 * x + 0]; w.y = tile[h][y][4 * x + 1];
        w.z = tile[h][y][4 * x + 2]; w.w = tile[h][y][4 * x + 3];
        __stcs(reinterpret_cast<float4*>(q + (size_t)(l0 + 32 * h + y) * CH), w);
    }
}

// ---------------- complex helpers (scalar) ----------------
__device__ __forceinline__ int PADi(int i) { return i + (i >> 4); }
__device__ __forceinline__ float2 cadd(float2 a, float2 b) { return make_float2(a.x + b.x, a.y + b.y); }
__device__ __forceinline__ float2 csub(float2 a, float2 b) { return make_float2(a.x - b.x, a.y - b.y); }
__device__ __forceinline__ float2 cmulf(float2 a, float2 b) {
    return make_float2(a.x * b.x - a.y * b.y, a.x * b.y + a.y * b.x);
}
__device__ __forceinline__ float2 mnegi(float2 a) { return make_float2(a.y, -a.x); } // a * (-i)
// a * (c - i s)
__device__ __forceinline__ float2 mulW(float2 a, float c, float s) {
    return make_float2(a.x * c + a.y * s, a.y * c - a.x * s);
}

__device__ __forceinline__ void radix8(const float2* c, float2* d) {
    float2 s0 = cadd(c[0], c[4]), s1 = csub(c[0], c[4]);
    float2 s2 = cadd(c[2], c[6]), s3 = mnegi(csub(c[2], c[6]));
    float2 E0 = cadd(s0, s2), E2 = csub(s0, s2);
    float2 E1 = cadd(s1, s3), E3 = csub(s1, s3);
    float2 u0 = cadd(c[1], c[5]), u1 = csub(c[1], c[5]);
    float2 u2 = cadd(c[3], c[7]), u3 = mnegi(csub(c[3], c[7]));
    float2 O0 = cadd(u0, u2), O2 = csub(u0, u2);
    float2 O1 = cadd(u1, u3), O3 = csub(u1, u3);
    const float r2 = 0.70710678118654752f;
    float2 T1 = make_float2(r2 * (O1.x + O1.y), r2 * (O1.y - O1.x));   // W8^1*O1
    float2 T2 = mnegi(O2);                                             // W8^2*O2
    float2 T3 = make_float2(r2 * (O3.y - O3.x), r2 * (-O3.x - O3.y));  // W8^3*O3
    d[0] = cadd(E0, O0); d[4] = csub(E0, O0);
    d[1] = cadd(E1, T1); d[5] = csub(E1, T1);
    d[2] = cadd(E2, T2); d[6] = csub(E2, T2);
    d[3] = cadd(E3, T3); d[7] = csub(E3, T3);
}

// in-place DFT-16 on v[0..15]
__device__ __forceinline__ void dft16_ip(float2* v) {
    float2 e[8], o[8];
#pragma unroll
    for (int r = 0; r < 8; r++) { e[r] = v[2 * r]; o[r] = v[2 * r + 1]; }
    float2 E[8], O[8];
    radix8(e, E);
    radix8(o, O);
    const float C1 = 0.92387953251128674f, S1 = 0.38268343236508978f;
    const float R2 = 0.70710678118654752f;
    float2 T[8];
    T[0] = O[0];
    T[1] = mulW(O[1], C1, S1);
    T[2] = mulW(O[2], R2, R2);
    T[3] = mulW(O[3], S1, C1);
    T[4] = mnegi(O[4]);
    T[5] = mnegi(mulW(O[5], C1, S1));
    T[6] = mnegi(mulW(O[6], R2, R2));
    T[7] = mnegi(mulW(O[7], S1, C1));
#pragma unroll
    for (int k = 0; k < 8; k++) {
        v[k]     = cadd(E[k], T[k]);
        v[k + 8] = csub(E[k], T[k]);
    }
}

// stage 1 variant A: input directly from GLOBAL (coalesced LDG.64, MLP=16)
__device__ __forceinline__ void stage1_from_global(const float2* __restrict__ gin,
                                                   float2* buf, int t) {
    float2 v[16];
#pragma unroll
    for (int r = 0; r < 16; r++) v[r] = __ldcs(&gin[t + (r << 7)]);
    dft16_ip(v);
    int dbase = t << 4;
#pragma unroll
    for (int r = 0; r < 16; r++) buf[PADi(dbase + r)] = v[r];
    __syncthreads();
}

// stage 1 variant B: in-place from smem
__device__ __forceinline__ void stage1_ip(float2* buf, int t) {
    float2 v[16];
#pragma unroll
    for (int r = 0; r < 16; r++) v[r] = buf[PADi(t + (r << 7))];
    dft16_ip(v);
    __syncthreads();
    int dbase = t << 4;
#pragma unroll
    for (int r = 0; r < 16; r++) buf[PADi(dbase + r)] = v[r];
    __syncthreads();
}

// stage 2: R=16, Ns=16, in place; twiddles from coalesced table g_tw2[r-1][m]
__device__ __forceinline__ void stage2_ip(float2* buf, int t) {
    float2 v[16];
#pragma unroll
    for (int r = 0; r < 16; r++) v[r] = buf[PADi(t + (r << 7))];
    int m = t & 15;
#pragma unroll
    for (int r = 1; r < 16; r++) v[r] = cmulf(v[r], g_tw2[((r - 1) << 4) + m]);
    dft16_ip(v);
    __syncthreads();
    int dbase = ((t >> 4) << 8) + (t & 15);
#pragma unroll
    for (int r = 0; r < 16; r++) buf[PADi(dbase + (r << 4))] = v[r];
    __syncthreads();
}

// stage 3: R=8, Ns=256, in place; twiddles from coalesced table g_tw3[r-1][j]
__device__ __forceinline__ void stage3_ip(float2* buf, int t) {
#pragma unroll
    for (int h = 0; h < 2; h++) {
        int j = t + (h << 7);   // 0..255
        float2 v[8], d[8];
#pragma unroll
        for (int r = 0; r < 8; r++) v[r] = buf[PADi(j + (r << 8))];
#pragma unroll
        for (int r = 1; r < 8; r++) v[r] = cmulf(v[r], g_tw3[((r - 1) << 8) + j]);
        radix8(v, d);
#pragma unroll
        for (int r = 0; r < 8; r++) buf[PADi(j + (r << 8))] = d[r];
    }
    __syncthreads();
}

// stage 3 variant: results go straight to GLOBAL with conj + 1/N scale
__device__ __forceinline__ void stage3_to_global(const float2* buf,
                                                 float2* __restrict__ gout, int t) {
    const float invn = 1.0f / (float)NF;
#pragma unroll
    for (int h = 0; h < 2; h++) {
        int j = t + (h << 7);   // 0..255
        float2 v[8], d[8];
#pragma unroll
        for (int r = 0; r < 8; r++) v[r] = buf[PADi(j + (r << 8))];
#pragma unroll
        for (int r = 1; r < 8; r++) v[r] = cmulf(v[r], g_tw3[((r - 1) << 8) + j]);
        radix8(v, d);
        // F = NF * conj(z') ; z'[n] = conj(F[n])/NF
#pragma unroll
        for (int r = 0; r < 8; r++)
            gout[j + (r << 8)] = make_float2(d[r].x * invn, -d[r].y * invn);
    }
}

// ---------------- main per-row kernel ----------------
__global__ void __launch_bounds__(NTHR, 8) fourier_rows_k() {
    __shared__ float2 buf[PADB];
    __shared__ unsigned hist[2][256];
    __shared__ unsigned selmask[65];
    __shared__ unsigned warpsum[4];
    __shared__ unsigned scal[2];

    int t = threadIdx.x;
    float2* rp2 = reinterpret_cast<float2*>(g_work + (size_t)blockIdx.x * LEN);

    // ---- forward FFT: stage1 straight from global (z[n] = x[2n] + i x[2n+1]) ----
    stage1_from_global(rp2, buf, t);
    stage2_ip(buf, t);
    stage3_ip(buf, t);          // Z in buf

    // rfft split, in place, pairwise (k, 2048-k); one thread owns both slots.
    // X[k] = E + W*O ; X[2048-k] = conj(E - W*O)
    for (int k = t; k <= NF / 2; k += NTHR) {
        float2 Zk = buf[PADi(k & (NF - 1))];
        float2 Zn = buf[PADi((NF - k) & (NF - 1))];
        float2 W  = g_tsplit[k];
        float2 E  = make_float2(0.5f * (Zk.x + Zn.x), 0.5f * (Zk.y - Zn.y));
        float2 D  = make_float2(Zk.x - Zn.x, Zk.y + Zn.y);
        float2 O  = make_float2(0.5f * D.y, -0.5f * D.x);   // D/(2i)
        float2 P  = cmulf(O, W);
        buf[PADi(k)]      = make_float2(E.x + P.x, E.y + P.y);
        buf[PADi(NF - k)] = make_float2(E.x - P.x, -(E.y - P.y));  // conj(E-P)
    }
    // zero select scratch while we're here (before the barrier)
    if (t < 65) selmask[t] = 0u;
    hist[0][t] = 0u; hist[0][t + 128] = 0u;
    __syncthreads();

    // keys = bits(|X|^2), thread t owns bins t*VPT .. t*VPT+VPT-1
    unsigned keys[VPT];
#pragma unroll
    for (int v = 0; v < VPT; v++) {
        int k = t * VPT + v;
        if (k <= NF) {
            float2 X = buf[PADi(k)];
            keys[v] = __float_as_uint(X.x * X.x + X.y * X.y);
        } else {
            keys[v] = 0u;
        }
    }

    // radix-select the TOPK-th largest key: 4 passes of 8 bits, MSB first.
    // Direct spread atomicAdd (no match_any — spread ATOMS ~2cyc/lane).
    // hist double-buffered: while warp0 scans hist[p], other threads zero hist[p^1].
    unsigned pref = 0u;
    int remain = TOPK;
#pragma unroll
    for (int pass = 0; pass < 4; pass++) {
        int shift = 24 - 8 * pass;
        int p = pass & 1;
        unsigned himask = (shift == 24) ? 0u : (0xFFFFFFFFu << (shift + 8));
#pragma unroll
        for (int v = 0; v < VPT; v++) {
            unsigned key = keys[v];
            bool cand = ((key & himask) == (pref & himask));
            if (pass == 0) {
                atomicAdd(&hist[p][(key >> shift) & 255u], 1u);
            } else {
                // skip whole warp-round if no lane has a candidate
                unsigned anyb = __ballot_sync(0xFFFFFFFFu, cand);
                if (anyb && cand)
                    atomicAdd(&hist[p][(key >> shift) & 255u], 1u);
            }
        }
        __syncthreads();
        if (t < 32) {
            unsigned cnts[8]; unsigned lsum = 0;
#pragma unroll
            for (int e = 0; e < 8; e++) { cnts[e] = hist[p][255 - (t * 8 + e)]; lsum += cnts[e]; }
            unsigned inc = lsum;
#pragma unroll
            for (int o = 1; o < 32; o <<= 1) {
                unsigned nn = __shfl_up_sync(0xFFFFFFFFu, inc, o);
                if (t >= o) inc += nn;
            }
            int excl = (int)(inc - lsum);  // keys strictly above this lane's range
            if (excl < remain && remain <= (int)inc) {
                int run = excl;
#pragma unroll
                for (int e = 0; e < 8; e++) {
                    if (run < remain && remain <= run + (int)cnts[e]) {
                        scal[0] = (unsigned)(255 - (t * 8 + e));
                        scal[1] = (unsigned)run;
                    }
                    run += (int)cnts[e];
                }
            }
        } else {
            // zero the other hist buffer for the next pass
            int q = p ^ 1;
            int i = t - 32;                       // 0..95
            hist[q][i] = 0u; hist[q][i + 96] = 0u;
            if (i < 64) hist[q][i + 192] = 0u;
        }
        __syncthreads();
        pref |= (scal[0] << shift);
        remain -= (int)scal[1];
    }
    unsigned Tkey = pref;   // exact key of the TOPK-th largest
    int extra = remain;     // ties (== Tkey) to keep, lowest bin index first

    // per-thread exclusive rank among ties (global order = bin index order)
    int local = 0;
#pragma unroll
    for (int v = 0; v < VPT; v++) {
        int k = t * VPT + v;
        if (k <= NF && keys[v] == Tkey) local++;
    }
    int inc2 = local;
#pragma unroll
    for (int o = 1; o < 32; o <<= 1) {
        int nn = __shfl_up_sync(0xFFFFFFFFu, inc2, o);
        if ((t & 31) >= o) inc2 += nn;
    }
    if ((t & 31) == 31) warpsum[t >> 5] = (unsigned)inc2;
    __syncthreads();
    if (t == 0) {
        unsigned acc = 0;
        for (int w = 0; w < 4; w++) { unsigned s = warpsum[w]; warpsum[w] = acc; acc += s; }
    }
    __syncthreads();
    int rank = (int)warpsum[t >> 5] + (inc2 - local);

    // build selection bitmask (only ~TOPK bits set -> few atomics)
#pragma unroll
    for (int v = 0; v < VPT; v++) {
        int k = t * VPT + v;
        if (k <= NF) {
            bool sel;
            if (keys[v] > Tkey) sel = true;
            else if (keys[v] == Tkey) { sel = (rank < extra); rank++; }
            else sel = false;
            if (sel) atomicOr(&selmask[k >> 5], 1u << (k & 31));
        }
    }
    __syncthreads();

    // rebuild conj(Z') from masked X, in place, pairwise; mask applied as predicate.
    for (int k = t; k <= NF / 2; k += NTHR) {
        bool sk = (selmask[k >> 5] >> (k & 31)) & 1u;
        int kn = NF - k;
        bool sn = (selmask[kn >> 5] >> (kn & 31)) & 1u;
        float2 Xk = buf[PADi(k)];
        float2 Xn = buf[PADi(kn)];   // k=0 -> Nyquist slot
        if (!sk) Xk = make_float2(0.f, 0.f);
        if (!sn) Xn = make_float2(0.f, 0.f);
        float2 W  = g_tsplit[k];
        float2 E  = make_float2(0.5f * (Xk.x + Xn.x), 0.5f * (Xk.y - Xn.y));
        float2 Dh = make_float2(0.5f * (Xk.x - Xn.x), 0.5f * (Xk.y + Xn.y)); // W^k O
        float2 O  = make_float2(Dh.x * W.x + Dh.y * W.y, Dh.y * W.x - Dh.x * W.y); // Dh*conj(W)
        float2 zck = make_float2(E.x - O.y, -(E.y + O.x));   // conj(Z'[k])
        float2 E2  = make_float2(0.5f * (Xn.x + Xk.x), 0.5f * (Xn.y - Xk.y));
        float2 Dh2 = make_float2(0.5f * (Xn.x - Xk.x), 0.5f * (Xn.y + Xk.y));
        float2 O2  = make_float2(-Dh2.x * W.x + Dh2.y * W.y, -Dh2.y * W.x - Dh2.x * W.y);
        float2 zcn = make_float2(E2.x - O2.y, -(E2.y + O2.x));
        buf[PADi(k)] = zck;
        if (k > 0) buf[PADi(NF - k)] = zcn;   // slot 2048 not part of Z'
    }
    __syncthreads();

    // ---- inverse FFT: F = FFT(conj(Z')) = NF * conj(z'); stage3 writes global ----
    stage1_ip(buf, t);
    stage2_ip(buf, t);
    stage3_to_global(buf, rp2, t);
}

// ---------------- launch ----------------
extern "C" void kernel_launch(void* const* d_in, const int* in_sizes, int n_in,
                              void* d_out, int out_size) {
    const float* x = (const float*)d_in[0];
    float* out = (float*)d_out;

    init_twiddles_k<<<(NF + 255) / 256, 256>>>();

    dim3 tb(8, 32);
    dim3 tg(LEN / 128, CH / 32, NB);
    transpose_in_k<<<tg, tb>>>(x);

    fourier_rows_k<<<NB * CH, NTHR>>>();

    transpose_out_k<<<tg, tb>>>(out);
}